// round 14
// baseline (speedup 1.0000x reference)
#include <cuda_runtime.h>
#include <math.h>

// Problem dims (fixed by the reference)
#define BB  8
#define HH  384
#define WW  768
#define HW_ (HH * WW)        // 294912
#define BHW (BB * HW_)       // 2359296

// Census geometry (proven R10 config): warp covers 32 columns (26 usable),
// thread strip = 24 rows, 4 warps/block.
#define CTX 26               // usable columns per block
#define CS  24               // rows per warp strip
#define CW  4                // warps per block
#define CTH (CS * CW)        // 96 rows per block
#define PW  38               // smem plane width
#define PH  (CTH + 6)        // 102 smem plane height
#define WPB (HW_ / 256)      // 1152 k_warp blocks per batch
#define FULLMASK 0xFFFFFFFFu

// ---------------------------------------------------------------------------
// Scratch (static __device__ arrays: no runtime allocation)
// ---------------------------------------------------------------------------
__device__ double g_acc[6];   // zero-initialized at load; k_final re-zeroes
// 0: photo_fw_sum, 1: photo_bw_sum, 2: mask_fw_sum, 3: mask_bw_sum,
// 4: census_fw_sum, 5: census_bw_sum

__device__ float2 g_ab_fw[BHW];  // {gray(img1), gray(warp(img2,ffw))}*255
__device__ float2 g_ab_bw[BHW];  // {gray(img2), gray(warp(img1,fbw))}*255
__device__ float  g_mask_fw[BHW];
__device__ float  g_mask_bw[BHW];

// ---------------------------------------------------------------------------
// Helpers
// ---------------------------------------------------------------------------
__device__ __forceinline__ float warp_red(float v) {
#pragma unroll
    for (int o = 16; o > 0; o >>= 1) v += __shfl_down_sync(FULLMASK, v, o);
    return v;
}

// bilinear coords (align_corners=True, border padding == clamp)
__device__ __forceinline__ void bilin(float gx, float gy,
                                      int& i00, int& i01, int& i10, int& i11,
                                      float& w00, float& w01, float& w10, float& w11) {
    gx = fminf(fmaxf(gx, 0.0f), (float)(WW - 1));
    gy = fminf(fmaxf(gy, 0.0f), (float)(HH - 1));
    float x0 = floorf(gx);
    float y0 = floorf(gy);
    float wx = gx - x0;
    float wy = gy - y0;
    int x0i = (int)x0;
    int y0i = (int)y0;
    int x1i = min(x0i + 1, WW - 1);
    int y1i = min(y0i + 1, HH - 1);
    i00 = y0i * WW + x0i;
    i01 = y0i * WW + x1i;
    i10 = y1i * WW + x0i;
    i11 = y1i * WW + x1i;
    w00 = (1.0f - wx) * (1.0f - wy);
    w01 = wx * (1.0f - wy);
    w10 = (1.0f - wx) * wy;
    w11 = wx * wy;
}

__device__ __forceinline__ float gather4(const float* __restrict__ p,
                                         int i00, int i01, int i10, int i11,
                                         float w00, float w01, float w10, float w11) {
    return __ldg(p + i00) * w00 + __ldg(p + i01) * w01 +
           __ldg(p + i10) * w10 + __ldg(p + i11) * w11;
}

// census tap distance — PROVEN form (2 independent rsqrt + rcp).
// Bit-exact antisymmetric under (c,n) swap.
__device__ __forceinline__ float tapdist(float2 n, float2 c) {
    float u = n.x - c.x;
    float v = n.y - c.y;
    float tA = u * rsqrtf(fmaf(u, u, 0.81f));
    float tB = v * rsqrtf(fmaf(v, v, 0.81f));
    float dt = tA - tB;
    float q = dt * dt;
    return __fdividef(q, 0.1f + q);
}

// ---------------------------------------------------------------------------
// K1: one batch of warps/masks/photometric/intensity. grid = 1152, block 256.
// ---------------------------------------------------------------------------
__global__ __launch_bounds__(256) void k_warp(
    const float* __restrict__ img1, const float* __restrict__ img2,
    const float* __restrict__ ffw,  const float* __restrict__ fbw,
    float* __restrict__ occ_out, int b) {

    const int r = blockIdx.x * blockDim.x + threadIdx.x;  // < HW_ exactly
    const int y = r / WW;
    const int x = r - y * WW;
    const int idx = b * HW_ + r;

    const float* ffb = ffw + b * 2 * HW_;
    const float* fbb = fbw + b * 2 * HW_;
    const float ffx = __ldg(ffb + r);
    const float ffy = __ldg(ffb + HW_ + r);
    const float fbx = __ldg(fbb + r);
    const float fby = __ldg(fbb + HW_ + r);

    // ---- forward-flow coordinates: warp img2 and flow_bw ----
    int a00, a01, a10, a11; float u00, u01, u10, u11;
    bilin(ffx + (float)x, ffy + (float)y, a00, a01, a10, a11, u00, u01, u10, u11);
    const float* i2b = img2 + b * 3 * HW_;
    float i2w0 = gather4(i2b,            a00, a01, a10, a11, u00, u01, u10, u11);
    float i2w1 = gather4(i2b + HW_,      a00, a01, a10, a11, u00, u01, u10, u11);
    float i2w2 = gather4(i2b + 2 * HW_,  a00, a01, a10, a11, u00, u01, u10, u11);
    float fbw_wx = gather4(fbb,          a00, a01, a10, a11, u00, u01, u10, u11);
    float fbw_wy = gather4(fbb + HW_,    a00, a01, a10, a11, u00, u01, u10, u11);

    // ---- backward-flow coordinates: warp img1 and flow_fw ----
    int c00, c01, c10, c11; float v00, v01, v10, v11;
    bilin(fbx + (float)x, fby + (float)y, c00, c01, c10, c11, v00, v01, v10, v11);
    const float* i1b = img1 + b * 3 * HW_;
    float i1w0 = gather4(i1b,            c00, c01, c10, c11, v00, v01, v10, v11);
    float i1w1 = gather4(i1b + HW_,      c00, c01, c10, c11, v00, v01, v10, v11);
    float i1w2 = gather4(i1b + 2 * HW_,  c00, c01, c10, c11, v00, v01, v10, v11);
    float ffw_wx = gather4(ffb,          c00, c01, c10, c11, v00, v01, v10, v11);
    float ffw_wy = gather4(ffb + HW_,    c00, c01, c10, c11, v00, v01, v10, v11);

    // ---- occlusion masks ----
    float d0 = ffx + fbw_wx, d1 = ffy + fbw_wy;
    float mag_f = d0 * d0 + d1 * d1;
    float fm_f = (ffx * ffx + ffy * ffy) + (fbw_wx * fbw_wx + fbw_wy * fbw_wy);
    float occ_f = (mag_f > 0.01f * fm_f + 0.5f) ? 1.0f : 0.0f;
    float mfw = 1.0f - occ_f;

    float e0 = fbx + ffw_wx, e1 = fby + ffw_wy;
    float mag_b = e0 * e0 + e1 * e1;
    float fm_b = (fbx * fbx + fby * fby) + (ffw_wx * ffw_wx + ffw_wy * ffw_wy);
    float occ_b = (mag_b > 0.01f * fm_b + 0.5f) ? 1.0f : 0.0f;
    float mbw = 1.0f - occ_b;

    // ---- photometric terms ----
    float i1c0 = __ldg(i1b + r);
    float i1c1 = __ldg(i1b + HW_ + r);
    float i1c2 = __ldg(i1b + 2 * HW_ + r);
    float i2c0 = __ldg(i2b + r);
    float i2c1 = __ldg(i2b + HW_ + r);
    float i2c2 = __ldg(i2b + 2 * HW_ + r);

    float pfw = (__powf(fabsf(i1c0 - i2w0) + 0.01f, 0.4f) +
                 __powf(fabsf(i1c1 - i2w1) + 0.01f, 0.4f) +
                 __powf(fabsf(i1c2 - i2w2) + 0.01f, 0.4f)) * mfw;
    float pbw = (__powf(fabsf(i2c0 - i1w0) + 0.01f, 0.4f) +
                 __powf(fabsf(i2c1 - i1w1) + 0.01f, 0.4f) +
                 __powf(fabsf(i2c2 - i1w2) + 0.01f, 0.4f)) * mbw;

    // ---- intensity planes (gray*255), interleaved per census pair ----
    float in1  = (0.2989f * i1c0 + 0.587f * i1c1 + 0.114f * i1c2) * 255.0f;
    float in2  = (0.2989f * i2c0 + 0.587f * i2c1 + 0.114f * i2c2) * 255.0f;
    float in2w = (0.2989f * i2w0 + 0.587f * i2w1 + 0.114f * i2w2) * 255.0f;
    float in1w = (0.2989f * i1w0 + 0.587f * i1w1 + 0.114f * i1w2) * 255.0f;
    g_ab_fw[idx] = make_float2(in1, in2w);
    g_ab_bw[idx] = make_float2(in2, in1w);
    g_mask_fw[idx] = mfw;
    g_mask_bw[idx] = mbw;
    occ_out[idx] = occ_f;

    // ---- block reduce 4 scalars, one double atomic each per block ----
    __shared__ float red[4][8];
    const int wid = threadIdx.x >> 5;
    const int lane = threadIdx.x & 31;
    float vals[4] = {pfw, pbw, mfw, mbw};
#pragma unroll
    for (int i = 0; i < 4; i++) {
        float v = warp_red(vals[i]);
        if (lane == 0) red[i][wid] = v;
    }
    __syncthreads();
    if (wid == 0) {
#pragma unroll
        for (int i = 0; i < 4; i++) {
            float v = (lane < 8) ? red[i][lane] : 0.0f;
            v = warp_red(v);
            if (lane == 0) atomicAdd(&g_acc[i], (double)v);
        }
    }
}

// ---------------------------------------------------------------------------
// K2: census loss for one batch. Inner loop byte-identical to the proven
// 209us version (rolled i=-3..23, predicate warm-up, explicit rotation,
// 24 independent shuffles, 3-MUFU tapdist). grid = (30, 4, 2), block (32,4).
// ---------------------------------------------------------------------------
__global__ __launch_bounds__(128) void k_census(int b) {
    const int pair = blockIdx.z;

    const float2* __restrict__ AB = (pair ? g_ab_bw : g_ab_fw) + b * HW_;
    const float*  __restrict__ M  = (pair ? g_mask_bw : g_mask_fw) + b * HW_;

    __shared__ float2 sAB[PH * PW];   // 102*38*8 = 31008 B

    const int tileX = blockIdx.x * CTX;
    const int tileY = blockIdx.y * CTH;
    const int tid = threadIdx.y * 32 + threadIdx.x;

    // ---- cooperative load of the A/B tile (zero-padded outside image) ----
    const float2 zz = make_float2(0.0f, 0.0f);
    for (int i = tid; i < PH * PW; i += 128) {
        int ly = i / PW;
        int lx = i - ly * PW;
        int gy = tileY + ly - 3;
        int gx = tileX + lx - 6;
        bool in = (gx >= 0) & (gx < WW) & (gy >= 0) & (gy < HH);
        sAB[i] = in ? __ldg(AB + gy * WW + gx) : zz;
    }
    __syncthreads();

    const int lane  = threadIdx.x;
    const int col   = lane + 3;                  // smem column of this lane
    const int gy0   = tileY + threadIdx.y * CS;  // first output row
    const int gxpix = tileX + lane - 3;          // this lane's image column
    const bool lane_valid = (lane >= 3) & (lane <= 28) & (gxpix < WW);

    // rolling history of positive-dy taps (ages 1..dy), constant-indexed
    float H1[7], H2a[7], H2b[7], H3a[7], H3b[7], H3c[7];
    float val = 0.0f;

    for (int i = -3; i < CS; i++) {
        const int r  = gy0 + i;                 // current tap/output row
        const int pr = r - tileY + 3;           // smem row of center
        const float2 c = sAB[pr * PW + col];

        // ---- positive-half taps at row r ----
        float Dc1[7], Dc2[7], Dc3[7];
#pragma unroll
        for (int dx = -3; dx <= 3; dx++)
            Dc3[dx + 3] = tapdist(sAB[(pr + 3) * PW + col + dx], c);
        if (i >= -2) {
#pragma unroll
            for (int dx = -3; dx <= 3; dx++)
                Dc2[dx + 3] = tapdist(sAB[(pr + 2) * PW + col + dx], c);
        }
        if (i >= -1) {
#pragma unroll
            for (int dx = -3; dx <= 3; dx++)
                Dc1[dx + 3] = tapdist(sAB[(pr + 1) * PW + col + dx], c);
        }

        if (i >= 0) {
            float D0[3];
#pragma unroll
            for (int dx = 1; dx <= 3; dx++)
                D0[dx - 1] = tapdist(sAB[pr * PW + col + dx], c);

            // own positive-half taps
            float acc = D0[0] + D0[1] + D0[2];
#pragma unroll
            for (int j = 0; j < 7; j++) acc += Dc1[j] + Dc2[j] + Dc3[j];

            // mirror taps: D(p-o, o) pulled from lane-dx at age dy
            // (24 independent shuffles — pipelines best)
#pragma unroll
            for (int dx = 1; dx <= 3; dx++)
                acc += __shfl_sync(FULLMASK, D0[dx - 1], lane - dx);
#pragma unroll
            for (int dx = -3; dx <= 3; dx++)
                acc += __shfl_sync(FULLMASK, H1[dx + 3], lane - dx);
#pragma unroll
            for (int dx = -3; dx <= 3; dx++)
                acc += __shfl_sync(FULLMASK, H2b[dx + 3], lane - dx);
#pragma unroll
            for (int dx = -3; dx <= 3; dx++)
                acc += __shfl_sync(FULLMASK, H3c[dx + 3], lane - dx);

            if (lane_valid) {
                float m = __ldg(M + r * WW + gxpix);
                val += __powf(acc + 0.01f, 0.4f) * m;
            }
        }

        // ---- rotate history ----
#pragma unroll
        for (int j = 0; j < 7; j++) {
            H3c[j] = H3b[j]; H3b[j] = H3a[j]; H3a[j] = Dc3[j];
            H2b[j] = H2a[j]; H2a[j] = Dc2[j];
            H1[j]  = Dc1[j];
        }
    }

    // ---- block reduce (4 warps) -> one double atomic ----
    __shared__ float red[4];
    const int wid = tid >> 5;
    float v = warp_red(val);
    if ((tid & 31) == 0) red[wid] = v;
    __syncthreads();
    if (tid == 0) {
        float w = red[0] + red[1] + red[2] + red[3];
        atomicAdd(&g_acc[4 + pair], (double)w);
    }
}

// ---------------------------------------------------------------------------
// K3: finalize scalars, then reset accumulators for the next invocation
// ---------------------------------------------------------------------------
__global__ void k_final(float* __restrict__ out) {
    double den_fw = 2.0 * g_acc[2] + 1e-6;
    double den_bw = 2.0 * g_acc[3] + 1e-6;
    double photo  = g_acc[0] / den_fw + g_acc[1] / den_bw;
    double census = g_acc[4] / den_fw + g_acc[5] / den_bw;
    out[0] = (float)(photo + census);
    out[1] = (float)photo;
    out[2] = (float)census;
#pragma unroll
    for (int i = 0; i < 6; i++) g_acc[i] = 0.0;
}

// ---------------------------------------------------------------------------
// Launch: fork-join DAG using ONLY pre-existing streams (null + per-thread;
// nothing created -> no device-memory delta). Census(b) depends on warp(b)
// via a reusable event; census batches pipeline on the per-thread stream
// while later warp batches run on the null stream. Join before k_final.
// ---------------------------------------------------------------------------
extern "C" void kernel_launch(void* const* d_in, const int* in_sizes, int n_in,
                              void* d_out, int out_size) {
    const float* img1 = (const float*)d_in[0];
    const float* img2 = (const float*)d_in[1];
    const float* ffw  = (const float*)d_in[2];
    const float* fbw  = (const float*)d_in[3];
    float* out = (float*)d_out;

    (void)in_sizes; (void)n_in; (void)out_size;

    cudaEvent_t eF, eJ;
    cudaEventCreateWithFlags(&eF, cudaEventDisableTiming);
    cudaEventCreateWithFlags(&eJ, cudaEventDisableTiming);

    dim3 g2(WW / CTX + ((WW % CTX) ? 1 : 0), HH / CTH, 2);  // (30, 4, 2)
    dim3 b2(32, 4, 1);
    for (int b = 0; b < BB; b++) {
        k_warp<<<WPB, 256>>>(img1, img2, ffw, fbw, out + 3, b);
        cudaEventRecord(eF, 0);
        cudaStreamWaitEvent(cudaStreamPerThread, eF, 0);
        k_census<<<g2, b2, 0, cudaStreamPerThread>>>(b);
    }
    cudaEventRecord(eJ, cudaStreamPerThread);
    cudaStreamWaitEvent(0, eJ, 0);
    k_final<<<1, 1>>>(out);

    cudaEventDestroy(eF);
    cudaEventDestroy(eJ);
}

// round 15
// speedup vs baseline: 1.8755x; 1.8755x over previous
#include <cuda_runtime.h>
#include <math.h>

// Problem dims (fixed by the reference)
#define BB  8
#define HH  384
#define WW  768
#define HW_ (HH * WW)        // 294912
#define BHW (BB * HW_)       // 2359296

// Census geometry: warp covers 32 columns (26 usable), thread strip = 24 rows
#define CTX 26               // usable columns per block
#define CS  24               // rows per warp strip
#define CW  4                // warps per block
#define CTH (CS * CW)        // 96 rows per block
#define PW  38               // smem plane width
#define PH  (CTH + 6)        // 102 smem plane height
#define FULLMASK 0xFFFFFFFFu

// ---------------------------------------------------------------------------
// Scratch (static __device__ arrays: no runtime allocation)
// ---------------------------------------------------------------------------
__device__ double g_acc[6];   // zero-initialized at load; k_final re-zeroes
// 0: photo_fw_sum, 1: photo_bw_sum, 2: mask_fw_sum, 3: mask_bw_sum,
// 4: census_fw_sum, 5: census_bw_sum

__device__ float2 g_ab_fw[BHW];  // {gray(img1), gray(warp(img2,ffw))}*255
__device__ float2 g_ab_bw[BHW];  // {gray(img2), gray(warp(img1,fbw))}*255
__device__ float  g_mask_fw[BHW];
__device__ float  g_mask_bw[BHW];

// ---------------------------------------------------------------------------
// Helpers
// ---------------------------------------------------------------------------
__device__ __forceinline__ float warp_red(float v) {
#pragma unroll
    for (int o = 16; o > 0; o >>= 1) v += __shfl_down_sync(FULLMASK, v, o);
    return v;
}

// bilinear coords (align_corners=True, border padding == clamp)
__device__ __forceinline__ void bilin(float gx, float gy,
                                      int& i00, int& i01, int& i10, int& i11,
                                      float& w00, float& w01, float& w10, float& w11) {
    gx = fminf(fmaxf(gx, 0.0f), (float)(WW - 1));
    gy = fminf(fmaxf(gy, 0.0f), (float)(HH - 1));
    float x0 = floorf(gx);
    float y0 = floorf(gy);
    float wx = gx - x0;
    float wy = gy - y0;
    int x0i = (int)x0;
    int y0i = (int)y0;
    int x1i = min(x0i + 1, WW - 1);
    int y1i = min(y0i + 1, HH - 1);
    i00 = y0i * WW + x0i;
    i01 = y0i * WW + x1i;
    i10 = y1i * WW + x0i;
    i11 = y1i * WW + x1i;
    w00 = (1.0f - wx) * (1.0f - wy);
    w01 = wx * (1.0f - wy);
    w10 = (1.0f - wx) * wy;
    w11 = wx * wy;
}

__device__ __forceinline__ float gather4(const float* __restrict__ p,
                                         int i00, int i01, int i10, int i11,
                                         float w00, float w01, float w10, float w11) {
    return __ldg(p + i00) * w00 + __ldg(p + i01) * w01 +
           __ldg(p + i10) * w10 + __ldg(p + i11) * w11;
}

// census tap distance — PROVEN form (2 independent rsqrt + rcp).
// Bit-exact antisymmetric under (c,n) swap.
__device__ __forceinline__ float tapdist(float2 n, float2 c) {
    float u = n.x - c.x;
    float v = n.y - c.y;
    float tA = u * rsqrtf(fmaf(u, u, 0.81f));
    float tB = v * rsqrtf(fmaf(v, v, 0.81f));
    float dt = tA - tB;
    float q = dt * dt;
    return __fdividef(q, 0.1f + q);
}

// ---------------------------------------------------------------------------
// K1: warps, occlusion masks, photometric loss terms, intensity planes
// (monolithic; at its L1tex roofline, ~68us)
// ---------------------------------------------------------------------------
__global__ __launch_bounds__(256) void k_warp(
    const float* __restrict__ img1, const float* __restrict__ img2,
    const float* __restrict__ ffw,  const float* __restrict__ fbw,
    float* __restrict__ occ_out) {

    const int idx = blockIdx.x * blockDim.x + threadIdx.x;  // < BHW exactly
    const int b = idx / HW_;
    const int r = idx - b * HW_;
    const int y = r / WW;
    const int x = r - y * WW;

    const float* ffb = ffw + b * 2 * HW_;
    const float* fbb = fbw + b * 2 * HW_;
    const float ffx = __ldg(ffb + r);
    const float ffy = __ldg(ffb + HW_ + r);
    const float fbx = __ldg(fbb + r);
    const float fby = __ldg(fbb + HW_ + r);

    // ---- forward-flow coordinates: warp img2 and flow_bw ----
    int a00, a01, a10, a11; float u00, u01, u10, u11;
    bilin(ffx + (float)x, ffy + (float)y, a00, a01, a10, a11, u00, u01, u10, u11);
    const float* i2b = img2 + b * 3 * HW_;
    float i2w0 = gather4(i2b,            a00, a01, a10, a11, u00, u01, u10, u11);
    float i2w1 = gather4(i2b + HW_,      a00, a01, a10, a11, u00, u01, u10, u11);
    float i2w2 = gather4(i2b + 2 * HW_,  a00, a01, a10, a11, u00, u01, u10, u11);
    float fbw_wx = gather4(fbb,          a00, a01, a10, a11, u00, u01, u10, u11);
    float fbw_wy = gather4(fbb + HW_,    a00, a01, a10, a11, u00, u01, u10, u11);

    // ---- backward-flow coordinates: warp img1 and flow_fw ----
    int c00, c01, c10, c11; float v00, v01, v10, v11;
    bilin(fbx + (float)x, fby + (float)y, c00, c01, c10, c11, v00, v01, v10, v11);
    const float* i1b = img1 + b * 3 * HW_;
    float i1w0 = gather4(i1b,            c00, c01, c10, c11, v00, v01, v10, v11);
    float i1w1 = gather4(i1b + HW_,      c00, c01, c10, c11, v00, v01, v10, v11);
    float i1w2 = gather4(i1b + 2 * HW_,  c00, c01, c10, c11, v00, v01, v10, v11);
    float ffw_wx = gather4(ffb,          c00, c01, c10, c11, v00, v01, v10, v11);
    float ffw_wy = gather4(ffb + HW_,    c00, c01, c10, c11, v00, v01, v10, v11);

    // ---- occlusion masks ----
    float d0 = ffx + fbw_wx, d1 = ffy + fbw_wy;
    float mag_f = d0 * d0 + d1 * d1;
    float fm_f = (ffx * ffx + ffy * ffy) + (fbw_wx * fbw_wx + fbw_wy * fbw_wy);
    float occ_f = (mag_f > 0.01f * fm_f + 0.5f) ? 1.0f : 0.0f;
    float mfw = 1.0f - occ_f;

    float e0 = fbx + ffw_wx, e1 = fby + ffw_wy;
    float mag_b = e0 * e0 + e1 * e1;
    float fm_b = (fbx * fbx + fby * fby) + (ffw_wx * ffw_wx + ffw_wy * ffw_wy);
    float occ_b = (mag_b > 0.01f * fm_b + 0.5f) ? 1.0f : 0.0f;
    float mbw = 1.0f - occ_b;

    // ---- photometric terms ----
    float i1c0 = __ldg(i1b + r);
    float i1c1 = __ldg(i1b + HW_ + r);
    float i1c2 = __ldg(i1b + 2 * HW_ + r);
    float i2c0 = __ldg(i2b + r);
    float i2c1 = __ldg(i2b + HW_ + r);
    float i2c2 = __ldg(i2b + 2 * HW_ + r);

    float pfw = (__powf(fabsf(i1c0 - i2w0) + 0.01f, 0.4f) +
                 __powf(fabsf(i1c1 - i2w1) + 0.01f, 0.4f) +
                 __powf(fabsf(i1c2 - i2w2) + 0.01f, 0.4f)) * mfw;
    float pbw = (__powf(fabsf(i2c0 - i1w0) + 0.01f, 0.4f) +
                 __powf(fabsf(i2c1 - i1w1) + 0.01f, 0.4f) +
                 __powf(fabsf(i2c2 - i1w2) + 0.01f, 0.4f)) * mbw;

    // ---- intensity planes (gray*255), interleaved per census pair ----
    float in1  = (0.2989f * i1c0 + 0.587f * i1c1 + 0.114f * i1c2) * 255.0f;
    float in2  = (0.2989f * i2c0 + 0.587f * i2c1 + 0.114f * i2c2) * 255.0f;
    float in2w = (0.2989f * i2w0 + 0.587f * i2w1 + 0.114f * i2w2) * 255.0f;
    float in1w = (0.2989f * i1w0 + 0.587f * i1w1 + 0.114f * i1w2) * 255.0f;
    g_ab_fw[idx] = make_float2(in1, in2w);
    g_ab_bw[idx] = make_float2(in2, in1w);
    g_mask_fw[idx] = mfw;
    g_mask_bw[idx] = mbw;
    occ_out[idx] = occ_f;

    // ---- block reduce 4 scalars, one double atomic each per block ----
    __shared__ float red[4][8];
    const int wid = threadIdx.x >> 5;
    const int lane = threadIdx.x & 31;
    float vals[4] = {pfw, pbw, mfw, mbw};
#pragma unroll
    for (int i = 0; i < 4; i++) {
        float v = warp_red(vals[i]);
        if (lane == 0) red[i][wid] = v;
    }
    __syncthreads();
    if (wid == 0) {
#pragma unroll
        for (int i = 0; i < 4; i++) {
            float v = (lane < 8) ? red[i][lane] : 0.0f;
            v = warp_red(v);
            if (lane == 0) atomicAdd(&g_acc[i], (double)v);
        }
    }
}

// ---------------------------------------------------------------------------
// K2: census loss via exact tap antisymmetry + warp-shuffle mirror sharing.
// R10 structure (rolled i=-3..23, predicate warm-up, 3-MUFU tapdist) with
// the mirror history compressed into a ring of partial sums:
//   P1[j] (consumable this row) = Dc3(r-3)+Dc2(r-2)+Dc1(r-1) for offset j
// Updates run AFTER consumption, so the shuffled P1 was formed a full row
// earlier (no same-row serialization like the failed R8 pre-sum).
// SHFL/row 24 -> 10; rotation MOVs 21 -> 7; history regs 42 -> 21.
// grid = (30, 4, 2*B), block (32,4).
// ---------------------------------------------------------------------------
__global__ __launch_bounds__(128) void k_census() {
    const int z = blockIdx.z;
    const int b = z & 7;
    const int pair = z >> 3;

    const float2* __restrict__ AB = (pair ? g_ab_bw : g_ab_fw) + b * HW_;
    const float*  __restrict__ M  = (pair ? g_mask_bw : g_mask_fw) + b * HW_;

    __shared__ float2 sAB[PH * PW];   // 102*38*8 = 31008 B

    const int tileX = blockIdx.x * CTX;
    const int tileY = blockIdx.y * CTH;
    const int tid = threadIdx.y * 32 + threadIdx.x;

    // ---- cooperative load of the A/B tile (zero-padded outside image) ----
    const float2 zz = make_float2(0.0f, 0.0f);
    for (int i = tid; i < PH * PW; i += 128) {
        int ly = i / PW;
        int lx = i - ly * PW;
        int gy = tileY + ly - 3;
        int gx = tileX + lx - 6;
        bool in = (gx >= 0) & (gx < WW) & (gy >= 0) & (gy < HH);
        sAB[i] = in ? __ldg(AB + gy * WW + gx) : zz;
    }
    __syncthreads();

    const int lane  = threadIdx.x;
    const int col   = lane + 3;                  // smem column of this lane
    const int gy0   = tileY + threadIdx.y * CS;  // first output row
    const int gxpix = tileX + lane - 3;          // this lane's image column
    const bool lane_valid = (lane >= 3) & (lane <= 28) & (gxpix < WW);

    // ring of mirror partial sums:
    //  P1: consumable at the current row;  P2/P3: forming for +1/+2 rows
    float P1[7], P2[7], P3[7];
#pragma unroll
    for (int j = 0; j < 7; j++) { P1[j] = 0.0f; P2[j] = 0.0f; P3[j] = 0.0f; }
    float val = 0.0f;

    for (int i = -3; i < CS; i++) {
        const int r  = gy0 + i;                 // current tap/output row
        const int pr = r - tileY + 3;           // smem row of center
        const float2 c = sAB[pr * PW + col];

        // ---- positive-half taps at row r ----
        float Dc1[7], Dc2[7], Dc3[7];
#pragma unroll
        for (int dx = -3; dx <= 3; dx++)
            Dc3[dx + 3] = tapdist(sAB[(pr + 3) * PW + col + dx], c);
        if (i >= -2) {
#pragma unroll
            for (int dx = -3; dx <= 3; dx++)
                Dc2[dx + 3] = tapdist(sAB[(pr + 2) * PW + col + dx], c);
        } else {
#pragma unroll
            for (int j = 0; j < 7; j++) Dc2[j] = 0.0f;
        }
        if (i >= -1) {
#pragma unroll
            for (int dx = -3; dx <= 3; dx++)
                Dc1[dx + 3] = tapdist(sAB[(pr + 1) * PW + col + dx], c);
        } else {
#pragma unroll
            for (int j = 0; j < 7; j++) Dc1[j] = 0.0f;
        }

        if (i >= 0) {
            float D0[3];
#pragma unroll
            for (int dx = 1; dx <= 3; dx++)
                D0[dx - 1] = tapdist(sAB[pr * PW + col + dx], c);

            // own positive-half taps
            float acc = D0[0] + D0[1] + D0[2];
#pragma unroll
            for (int j = 0; j < 7; j++) acc += Dc1[j] + Dc2[j] + Dc3[j];

            // same-row mirrors (dy=0): raw shuffles of this row's D0
#pragma unroll
            for (int dx = 1; dx <= 3; dx++)
                acc += __shfl_sync(FULLMASK, D0[dx - 1], lane - dx);
            // aged mirrors (dy=1..3): one shuffle per dx of the ring sum
            // (P1 was fully formed at the end of the previous row)
#pragma unroll
            for (int j = 0; j < 7; j++)
                acc += __shfl_sync(FULLMASK, P1[j], lane - (j - 3));

            if (lane_valid) {
                float m = __ldg(M + r * WW + gxpix);
                val += __powf(acc + 0.01f, 0.4f) * m;
            }
        }

        // ---- ring update (off the critical path; feeds NEXT row) ----
#pragma unroll
        for (int j = 0; j < 7; j++) {
            P1[j] = P2[j] + Dc1[j];
            P2[j] = P3[j] + Dc2[j];
            P3[j] = Dc3[j];
        }
    }

    // ---- block reduce (4 warps) -> one double atomic ----
    __shared__ float red[4];
    const int wid = tid >> 5;
    float v = warp_red(val);
    if ((tid & 31) == 0) red[wid] = v;
    __syncthreads();
    if (tid == 0) {
        float w = red[0] + red[1] + red[2] + red[3];
        atomicAdd(&g_acc[4 + pair], (double)w);
    }
}

// ---------------------------------------------------------------------------
// K3: finalize scalars, then reset accumulators for the next invocation
// ---------------------------------------------------------------------------
__global__ void k_final(float* __restrict__ out) {
    double den_fw = 2.0 * g_acc[2] + 1e-6;
    double den_bw = 2.0 * g_acc[3] + 1e-6;
    double photo  = g_acc[0] / den_fw + g_acc[1] / den_bw;
    double census = g_acc[4] / den_fw + g_acc[5] / den_bw;
    out[0] = (float)(photo + census);
    out[1] = (float)photo;
    out[2] = (float)census;
#pragma unroll
    for (int i = 0; i < 6; i++) g_acc[i] = 0.0;
}

// ---------------------------------------------------------------------------
// Launch (monolithic; no created streams/events)
// ---------------------------------------------------------------------------
extern "C" void kernel_launch(void* const* d_in, const int* in_sizes, int n_in,
                              void* d_out, int out_size) {
    const float* img1 = (const float*)d_in[0];
    const float* img2 = (const float*)d_in[1];
    const float* ffw  = (const float*)d_in[2];
    const float* fbw  = (const float*)d_in[3];
    float* out = (float*)d_out;

    (void)in_sizes; (void)n_in; (void)out_size;

    k_warp<<<BHW / 256, 256>>>(img1, img2, ffw, fbw, out + 3);
    dim3 g2(WW / CTX + ((WW % CTX) ? 1 : 0), HH / CTH, 2 * BB);  // (30, 4, 16)
    dim3 b2(32, 4, 1);
    k_census<<<g2, b2>>>();
    k_final<<<1, 1>>>(out);
}